// round 10
// baseline (speedup 1.0000x reference)
#include <cuda_runtime.h>
#include <cstdint>

// out[c, i, j, k, l] = tb[c,0,i] * tb[c,1,j] * tb[c,2,k] * tb[c,3,l]
// tb = tensor + bias, shapes (C=2048, 4, 16). Output (C, 16,16,16,16) fp32.
//
// Pure store-bandwidth kernel: 512 MB out, ~1 MB in.
// R10 = R9 (32768 CTAs, one 16KB i-slice, smem tile, cp.async.bulk egress)
// but with PER-WARP bulk stores: each warp owns two contiguous 1KB spans of
// the tile; after its own STS + __syncwarp + fence.proxy.async it issues
// its own cp.async.bulk pair and waits on its own bulk-group. Removes the
// block-wide pre-store barrier and the single-thread 16KB serialization —
// store egress starts ~8x earlier in CTA life.

static constexpr int LDIM = 16;
static constexpr int NFAC = 4;
static constexpr int THREADS = 256;
static constexpr int TILE_FLOATS = 4096;            // 16 KB

__global__ __launch_bounds__(THREADS, 8)
void tpe_kernel(const float* __restrict__ tensor,
                const float* __restrict__ bias,
                float* __restrict__ out)
{
    __shared__ float s[NFAC * LDIM];
    __shared__ __align__(128) float tile[TILE_FLOATS];

    const int b = blockIdx.x;
    const int c = b >> 4;          // channel
    const int i = b & 15;          // i slice: this CTA writes out[c, i, :, :, :]
    const int t = threadIdx.x;
    const int w = t >> 5;          // warp id
    const int lane = t & 31;

    if (t < NFAC * LDIM) {
        const int g = c * (NFAC * LDIM) + t;
        s[t] = tensor[g] + bias[g];
    }
    __syncthreads();

    // float8 index within the i-slice: r = t + 256*jh, jh in {0,1}.
    //   l-half lh = r & 1, k = (r>>1) & 15, jlow = (r>>5) & 7 (from t);
    //   j = jlow | (jh<<3).
    const int lh   = t & 1;
    const int k    = (t >> 1) & 15;
    const int jlow = (t >> 5) & 7;

    const float p2 = s[2 * LDIM + k];
    float v3[8];
    #pragma unroll
    for (int m = 0; m < 8; ++m) v3[m] = s[3 * LDIM + lh * 8 + m];

    const float a0 = s[i] * p2;

    // Thread's 2 float4 slots per jh half; warp w covers floats
    // [w*256, w*256+256) and [2048 + w*256, ...): two contiguous 1KB spans.
    float4* tp = reinterpret_cast<float4*>(tile) + t * 2;

    #pragma unroll
    for (int jh = 0; jh < 2; ++jh) {
        const float a = a0 * s[LDIM + jlow + (jh << 3)];
        float4 w0, w1;
        w0.x = a * v3[0]; w0.y = a * v3[1]; w0.z = a * v3[2]; w0.w = a * v3[3];
        w1.x = a * v3[4]; w1.y = a * v3[5]; w1.z = a * v3[6]; w1.w = a * v3[7];
        tp[jh * 512 + 0] = w0;
        tp[jh * 512 + 1] = w1;
    }

    // Warp-local egress: this warp's STS are visible to the async proxy
    // after __syncwarp + fence; elected lane ships the warp's two 1KB spans.
    __syncwarp();
    if (lane == 0) {
        asm volatile("fence.proxy.async.shared::cta;" ::: "memory");
        const float* src0 = tile + w * 256;
        const float* src1 = tile + 2048 + w * 256;
        float* g0 = out + (size_t)c * 65536 + (size_t)i * 4096 + (size_t)w * 256;
        float* g1 = g0 + 2048;

        uint32_t sa0, sa1;
        asm("{ .reg .u64 a; cvta.to.shared.u64 a, %1; cvt.u32.u64 %0, a; }"
            : "=r"(sa0) : "l"(src0));
        asm("{ .reg .u64 a; cvta.to.shared.u64 a, %1; cvt.u32.u64 %0, a; }"
            : "=r"(sa1) : "l"(src1));

        asm volatile(
            "cp.async.bulk.global.shared::cta.bulk_group [%0], [%1], %2;"
            :: "l"(g0), "r"(sa0), "r"(1024) : "memory");
        asm volatile(
            "cp.async.bulk.global.shared::cta.bulk_group [%0], [%1], %2;"
            :: "l"(g1), "r"(sa1), "r"(1024) : "memory");
        asm volatile("cp.async.bulk.commit_group;" ::: "memory");
        asm volatile("cp.async.bulk.wait_group 0;" ::: "memory");
    }
}

extern "C" void kernel_launch(void* const* d_in, const int* in_sizes, int n_in,
                              void* d_out, int out_size)
{
    const float* tensor = (const float*)d_in[0];
    const float* bias   = (const float*)d_in[1];
    float* out          = (float*)d_out;

    const int C = in_sizes[0] / (NFAC * LDIM);   // 2048

    tpe_kernel<<<C * 16, THREADS>>>(tensor, bias, out);
}